// round 10
// baseline (speedup 1.0000x reference)
#include <cuda_runtime.h>
#include <cuda_bf16.h>

// PositionalEncoding: out[pos,2i]=sin(pos*w_i), out[pos,2i+1]=cos(pos*w_i),
// w_i = 10000^{-i/512}, d_model=1024, seq_len = out_size/1024. X unused.
//
// R9 conclusion: the kernel is pinned at the chip's *write* throughput cap
// (~2400 B/cyc, ~37% of LTS peak) — verified path-independent across
// per-thread STG (5 configs) and cp.async.bulk; dur invariant at 7.4-8.0us
// for 33.5MB of output regardless of occupancy (36-77%) or compute (4x).
// Floor ~7.3us. Final config: finest granularity (1 row per block,
// grid=8192), direct evaluation, no loop/sync — best measured structure.
//
// Seed math (verified 6e-5 rel err): angle = fp32 product pos*w (same as
// the JAX reference), 2-term Cody-Waite reduction mod 2pi (C1 exact in 9
// bits -> both FMAs exact; residual ~2e-7 rad), then MUFU __sincosf.

#define D_MODEL 1024
#define THREADS 256                    // thread t owns pair cols 2t, 2t+1
#define ROW_F4  (D_MODEL / 4)          // 256 float4 per row

#define NEG_K2    (-0.02595256324130752f)   // -log2(10000)/512
#define INV_2PI   (0.15915494309189535f)
#define TWO_PI_HI (6.28125f)                // exact in 9 mantissa bits
#define TWO_PI_LO (0.0019353071795864769f)  // 2pi - TWO_PI_HI

__device__ __forceinline__ void sincos_big(float theta, float* s, float* c) {
    // theta in [0, ~8200): 2-term Cody-Waite reduction mod 2pi, then MUFU.
    float n = rintf(theta * INV_2PI);
    float r = fmaf(-n, TWO_PI_HI, theta);
    r = fmaf(-n, TWO_PI_LO, r);
    __sincosf(r, s, c);
}

__global__ __launch_bounds__(THREADS, 8)
void pe_kernel(float4* __restrict__ out, int seq_len) {
    const int t   = threadIdx.x;
    const int pos = blockIdx.x;
    if (pos >= seq_len) return;

    // Inverse frequencies for this thread's two pair-columns.
    const float w0 = exp2f((float)(2 * t)     * NEG_K2);
    const float w1 = exp2f((float)(2 * t + 1) * NEG_K2);

    const float fp = (float)pos;

    // Two independent reduced sincos evaluations (MUFU pipelined).
    float s0, c0, s1, c1;
    sincos_big(fp * w0, &s0, &c0);
    sincos_big(fp * w1, &s1, &c1);

    out[(size_t)pos * ROW_F4 + t] = make_float4(s0, c0, s1, c1);
}

extern "C" void kernel_launch(void* const* d_in, const int* in_sizes, int n_in,
                              void* d_out, int out_size) {
    (void)d_in; (void)in_sizes; (void)n_in;
    const int seq_len = out_size / D_MODEL;    // 8192
    float4* out = (float4*)d_out;

    pe_kernel<<<seq_len, THREADS>>>(out, seq_len);   // one row per block
}

// round 11
// speedup vs baseline: 1.2657x; 1.2657x over previous
#include <cuda_runtime.h>
#include <cuda_bf16.h>

// PositionalEncoding: out[pos,2i]=sin(pos*w_i), out[pos,2i+1]=cos(pos*w_i),
// w_i = 10000^{-i/512}, d_model=1024, seq_len = out_size/1024. X unused.
//
// FINAL (R10): six configurations (STG at occ 36-77%, cp.async.bulk,
// grids 512..8192) all pin at L2~36-39% => pure-write-stream cap
// ~2400 B/cyc, path-independent. Floor ~7.3us for 33.5MB; best measured
// config (rows=4, grid=2048, dual rotation chains) runs 7.42us = 98% of
// floor. This round: that config + __stcs (evict-first streaming stores,
// output is write-once never-read) as the last free micro-lever.
//
// Math (verified 6.8e-5 rel err): seed angle = fp32 product pos*w (same as
// the JAX ref), 2-term Cody-Waite mod-2pi reduction (both FMAs exact,
// residual ~2e-7 rad) + MUFU __sincosf; then 2 independent rotation chains
// (even/odd rows) stepping by double angle 2w (4 FMA/row, depth 2).

#define D_MODEL 1024
#define THREADS 256                    // thread t owns pair cols 2t, 2t+1
#define ROWS_PER_BLOCK 4
#define ROW_F4  (D_MODEL / 4)          // 256 float4 per row

#define NEG_K2    (-0.02595256324130752f)   // -log2(10000)/512
#define INV_2PI   (0.15915494309189535f)
#define TWO_PI_HI (6.28125f)                // exact in 9 mantissa bits
#define TWO_PI_LO (0.0019353071795864769f)  // 2pi - TWO_PI_HI

__device__ __forceinline__ void sincos_big(float theta, float* s, float* c) {
    float n = rintf(theta * INV_2PI);
    float r = fmaf(-n, TWO_PI_HI, theta);
    r = fmaf(-n, TWO_PI_LO, r);
    __sincosf(r, s, c);
}

__global__ __launch_bounds__(THREADS, 8)
void pe_kernel(float4* __restrict__ out, int seq_len) {
    const int t = threadIdx.x;

    const float w0 = exp2f((float)(2 * t)     * NEG_K2);
    const float w1 = exp2f((float)(2 * t + 1) * NEG_K2);

    const int row0 = blockIdx.x * ROWS_PER_BLOCK;
    if (row0 >= seq_len) return;

    // Chain A seed: even rows.
    float sA0, cA0, sA1, cA1;
    sincos_big((float)row0 * w0, &sA0, &cA0);
    sincos_big((float)row0 * w1, &sA1, &cA1);

    // 1-row step (w <= 1 rad): MUFU path.
    float sw0, cw0, sw1, cw1;
    __sincosf(w0, &sw0, &cw0);
    __sincosf(w1, &sw1, &cw1);

    // Chain B seed = chain A rotated one row.
    float sB0 = fmaf(sA0, cw0,  cA0 * sw0);
    float cB0 = fmaf(cA0, cw0, -sA0 * sw0);
    float sB1 = fmaf(sA1, cw1,  cA1 * sw1);
    float cB1 = fmaf(cA1, cw1, -sA1 * sw1);

    // 2-row step via double-angle.
    const float s20 = 2.0f * sw0 * cw0;
    const float c20 = fmaf(-2.0f * sw0, sw0, 1.0f);
    const float s21 = 2.0f * sw1 * cw1;
    const float c21 = fmaf(-2.0f * sw1, sw1, 1.0f);

    float4* p = out + (size_t)row0 * ROW_F4 + t;

    if (row0 + ROWS_PER_BLOCK <= seq_len) {
        #pragma unroll
        for (int r = 0; r < ROWS_PER_BLOCK / 2; r++) {
            __stcs(p,          make_float4(sA0, cA0, sA1, cA1));  // even row
            __stcs(p + ROW_F4, make_float4(sB0, cB0, sB1, cB1));  // odd row
            p += 2 * ROW_F4;
            float nsA0 = fmaf(sA0, c20,  cA0 * s20);
            float ncA0 = fmaf(cA0, c20, -sA0 * s20);
            float nsA1 = fmaf(sA1, c21,  cA1 * s21);
            float ncA1 = fmaf(cA1, c21, -sA1 * s21);
            float nsB0 = fmaf(sB0, c20,  cB0 * s20);
            float ncB0 = fmaf(cB0, c20, -sB0 * s20);
            float nsB1 = fmaf(sB1, c21,  cB1 * s21);
            float ncB1 = fmaf(cB1, c21, -sB1 * s21);
            sA0 = nsA0; cA0 = ncA0; sA1 = nsA1; cA1 = ncA1;
            sB0 = nsB0; cB0 = ncB0; sB1 = nsB1; cB1 = ncB1;
        }
    } else {
        const int rows = seq_len - row0;
        for (int r = 0; r < rows; r += 2) {
            __stcs(p, make_float4(sA0, cA0, sA1, cA1));
            if (r + 1 < rows) __stcs(p + ROW_F4, make_float4(sB0, cB0, sB1, cB1));
            p += 2 * ROW_F4;
            float nsA0 = fmaf(sA0, c20,  cA0 * s20);
            float ncA0 = fmaf(cA0, c20, -sA0 * s20);
            float nsA1 = fmaf(sA1, c21,  cA1 * s21);
            float ncA1 = fmaf(cA1, c21, -sA1 * s21);
            float nsB0 = fmaf(sB0, c20,  cB0 * s20);
            float ncB0 = fmaf(cB0, c20, -sB0 * s20);
            float nsB1 = fmaf(sB1, c21,  cB1 * s21);
            float ncB1 = fmaf(cB1, c21, -sB1 * s21);
            sA0 = nsA0; cA0 = ncA0; sA1 = nsA1; cA1 = ncA1;
            sB0 = nsB0; cB0 = ncB0; sB1 = nsB1; cB1 = ncB1;
        }
    }
}

extern "C" void kernel_launch(void* const* d_in, const int* in_sizes, int n_in,
                              void* d_out, int out_size) {
    (void)d_in; (void)in_sizes; (void)n_in;
    const int seq_len = out_size / D_MODEL;    // 8192
    float4* out = (float4*)d_out;

    const int grid = (seq_len + ROWS_PER_BLOCK - 1) / ROWS_PER_BLOCK;  // 2048
    pe_kernel<<<grid, THREADS>>>(out, seq_len);
}